// round 4
// baseline (speedup 1.0000x reference)
#include <cuda_runtime.h>
#include <cstdint>
#include <math.h>

#define HID 1024
#define BATCH 32
#define SEQ 512
#define GATES 4096            // 4*HID
#define MTOT (BATCH*SEQ)      // 16384
#define NBLK 128              // recurrent blocks (HID/8)

// ---------------- device scratch (allocation-free rule: __device__ globals) ----
__device__ float g_xg[(size_t)MTOT * GATES];     // 268 MB: x@Wx + bias, [m][4096]
__device__ float g_wpack[(size_t)HID * 32 * NBLK]; // 16 MB: per-block packed Wh
__device__ float g_hbuf[2][HID * BATCH];         // ping-pong h, layout [hid][batch]
__device__ unsigned int g_bar_count;
__device__ unsigned int g_bar_gen;

// ---------------- packed f32x2 helpers ----------------------------------------
__device__ __forceinline__ unsigned long long pk2(float lo, float hi) {
    unsigned long long r;
    asm("mov.b64 %0, {%1, %2};" : "=l"(r) : "f"(lo), "f"(hi));
    return r;
}
__device__ __forceinline__ void upk2(unsigned long long v, float& lo, float& hi) {
    asm("mov.b64 {%0, %1}, %2;" : "=f"(lo), "=f"(hi) : "l"(v));
}
__device__ __forceinline__ void fma2(unsigned long long& c,
                                     unsigned long long a, unsigned long long b) {
    asm("fma.rn.f32x2 %0, %1, %2, %3;" : "=l"(c) : "l"(a), "l"(b), "l"(c));
}

__device__ __forceinline__ float sigmoidf_(float x) {
    return 1.0f / (1.0f + expf(-x));
}

// ---------------- kernel 0: pack Wh into per-block contiguous layout ----------
// g_wpack[j][k][col], col = gate*8 + hl  <->  Wh[k][gate*1024 + j*8 + hl]
__global__ void repack_wh(const float* __restrict__ wh) {
    int j = blockIdx.x;                       // 0..127
    float* dst = g_wpack + (size_t)j * HID * 32;
    for (int idx = threadIdx.x; idx < HID * 32; idx += blockDim.x) {
        int k    = idx >> 5;
        int col  = idx & 31;
        int gate = col >> 3;
        int hl   = col & 7;
        dst[idx] = wh[(size_t)k * GATES + gate * HID + j * 8 + hl];
    }
}

// ---------------- kernel 1: xg = x @ Wx + bias  (16384 x 1024 x 4096) ---------
// 128x128 block tile, K-chunk 16, 256 threads, 8x8 per-thread tile via f32x2.
__global__ __launch_bounds__(256, 2)
void gemm_xg(const float* __restrict__ Amat,   // [16384][1024]
             const float* __restrict__ Bmat,   // [1024][4096]
             const float* __restrict__ bias) { // [4096]
    __shared__ float As[16][128];   // transposed: As[k][m]
    __shared__ float Bs[16][128];   // Bs[k][n]

    const int tid = threadIdx.x;
    const int tx = tid & 15, ty = tid >> 4;
    const int m0 = blockIdx.y * 128, n0 = blockIdx.x * 128;

    unsigned long long acc[8][4];
    #pragma unroll
    for (int i = 0; i < 8; i++)
        #pragma unroll
        for (int jj = 0; jj < 4; jj++) acc[i][jj] = 0ULL;

    // staging indices
    const int a0row = tid >> 2;            // 0..63
    const int aK    = (tid & 3) * 4;       // 0,4,8,12
    const int b0row = tid >> 5;            // 0..7
    const int bC    = (tid & 31) * 4;      // 0..124

    float4 pa0, pa1, pb0, pb1;

    // prefetch chunk 0
    pa0 = *(const float4*)(Amat + (size_t)(m0 + a0row)      * HID + 0 + aK);
    pa1 = *(const float4*)(Amat + (size_t)(m0 + a0row + 64) * HID + 0 + aK);
    pb0 = *(const float4*)(Bmat + (size_t)(0 + b0row)     * GATES + n0 + bC);
    pb1 = *(const float4*)(Bmat + (size_t)(0 + b0row + 8) * GATES + n0 + bC);

    for (int k0 = 0; k0 < HID; k0 += 16) {
        // store staged chunk to smem (A transposed)
        As[aK + 0][a0row] = pa0.x; As[aK + 1][a0row] = pa0.y;
        As[aK + 2][a0row] = pa0.z; As[aK + 3][a0row] = pa0.w;
        As[aK + 0][a0row + 64] = pa1.x; As[aK + 1][a0row + 64] = pa1.y;
        As[aK + 2][a0row + 64] = pa1.z; As[aK + 3][a0row + 64] = pa1.w;
        *(float4*)&Bs[b0row][bC]     = pb0;
        *(float4*)&Bs[b0row + 8][bC] = pb1;
        __syncthreads();

        if (k0 + 16 < HID) {   // prefetch next chunk into registers
            pa0 = *(const float4*)(Amat + (size_t)(m0 + a0row)      * HID + k0 + 16 + aK);
            pa1 = *(const float4*)(Amat + (size_t)(m0 + a0row + 64) * HID + k0 + 16 + aK);
            pb0 = *(const float4*)(Bmat + (size_t)(k0 + 16 + b0row)     * GATES + n0 + bC);
            pb1 = *(const float4*)(Bmat + (size_t)(k0 + 16 + b0row + 8) * GATES + n0 + bC);
        }

        #pragma unroll
        for (int kk = 0; kk < 16; kk++) {
            float4 a0 = *(const float4*)&As[kk][ty * 8];
            float4 a1 = *(const float4*)&As[kk][ty * 8 + 4];
            float4 b0 = *(const float4*)&Bs[kk][tx * 8];
            float4 b1 = *(const float4*)&Bs[kk][tx * 8 + 4];
            unsigned long long bp[4] = { pk2(b0.x, b0.y), pk2(b0.z, b0.w),
                                         pk2(b1.x, b1.y), pk2(b1.z, b1.w) };
            float av[8] = { a0.x, a0.y, a0.z, a0.w, a1.x, a1.y, a1.z, a1.w };
            #pragma unroll
            for (int i = 0; i < 8; i++) {
                unsigned long long a2 = pk2(av[i], av[i]);
                #pragma unroll
                for (int jj = 0; jj < 4; jj++) fma2(acc[i][jj], a2, bp[jj]);
            }
        }
        __syncthreads();
    }

    // epilogue: add bias, store to g_xg
    #pragma unroll
    for (int i = 0; i < 8; i++) {
        int m = m0 + ty * 8 + i;
        float* crow = g_xg + (size_t)m * GATES;
        #pragma unroll
        for (int jj = 0; jj < 4; jj++) {
            float lo, hi;
            upk2(acc[i][jj], lo, hi);
            int n = n0 + tx * 8 + jj * 2;
            crow[n]     = lo + bias[n];
            crow[n + 1] = hi + bias[n + 1];
        }
    }
}

// ---------------- kernel 2: persistent recurrence -----------------------------
// 128 blocks x 256 threads. Block j owns hidden cols [j*8, j*8+8), all 4 gates,
// all 32 batches. c lives in registers (1 per thread). h ping-pongs in global.
__global__ __launch_bounds__(256, 1)
void lstm_rec(const float* __restrict__ xg,    // g_xg
              const float* __restrict__ wpk,   // g_wpack
              float* __restrict__ out) {       // [32][512][1024]
    __shared__ float hbuf[64 * 32];            // h chunk: [kk][batch]
    __shared__ float wbuf[64 * 32];            // w chunk: [kk][col]
    __shared__ float part[8][32][32];          // per-warp split-K partials

    const int tid  = threadIdx.x;
    const int warp = tid >> 5, lane = tid & 31;
    const int bg = lane >> 2;                  // batch group: batches bg*4..bg*4+3
    const int cg = lane & 3;                   // col group:  cols cg*8..cg*8+7
    const int j = blockIdx.x, hid0 = j * 8;
    const int b = tid >> 3, hl = tid & 7;      // update-phase mapping
    const float* wblk = wpk + (size_t)j * HID * 32;

    float c_reg = 0.0f;
    const unsigned start_gen = *((volatile unsigned int*)&g_bar_gen);

    for (int t = 0; t < SEQ; t++) {
        float gate[4];

        if (t == 0) {
            const float* xgrow = xg + ((size_t)b * SEQ + t) * GATES + hid0;
            #pragma unroll
            for (int g = 0; g < 4; g++) gate[g] = xgrow[g * HID + hl];
        } else {
            unsigned long long acc2[4][4];
            #pragma unroll
            for (int bi = 0; bi < 4; bi++)
                #pragma unroll
                for (int cj = 0; cj < 4; cj++) acc2[bi][cj] = 0ULL;

            const float* hsrc = g_hbuf[t & 1];
            for (int k0 = 0; k0 < HID; k0 += 64) {
                // stage 64x32 of h (L2-coherent: skip L1, it can be stale
                // within this persistent launch) and 64x32 of packed W
                ((float4*)hbuf)[tid]       = __ldcg(((const float4*)(hsrc + k0 * 32)) + tid);
                ((float4*)hbuf)[tid + 256] = __ldcg(((const float4*)(hsrc + k0 * 32)) + tid + 256);
                ((float4*)wbuf)[tid]       = *(((const float4*)(wblk + k0 * 32)) + tid);
                ((float4*)wbuf)[tid + 256] = *(((const float4*)(wblk + k0 * 32)) + tid + 256);
                __syncthreads();

                #pragma unroll
                for (int kk2 = 0; kk2 < 8; kk2++) {
                    int kk = warp * 8 + kk2;           // split-K across warps
                    float4 h4 = *(const float4*)&hbuf[kk * 32 + bg * 4];
                    float4 w0 = *(const float4*)&wbuf[kk * 32 + cg * 8];
                    float4 w1 = *(const float4*)&wbuf[kk * 32 + cg * 8 + 4];
                    unsigned long long wp[4] = { pk2(w0.x, w0.y), pk2(w0.z, w0.w),
                                                 pk2(w1.x, w1.y), pk2(w1.z, w1.w) };
                    float hv[4] = { h4.x, h4.y, h4.z, h4.w };
                    #pragma unroll
                    for (int bi = 0; bi < 4; bi++) {
                        unsigned long long a2 = pk2(hv[bi], hv[bi]);
                        #pragma unroll
                        for (int cj = 0; cj < 4; cj++) fma2(acc2[bi][cj], a2, wp[cj]);
                    }
                }
                __syncthreads();
            }

            // split-K reduction via smem
            #pragma unroll
            for (int bi = 0; bi < 4; bi++) {
                #pragma unroll
                for (int cj = 0; cj < 4; cj++) {
                    float lo, hi;
                    upk2(acc2[bi][cj], lo, hi);
                    part[warp][bg * 4 + bi][cg * 8 + cj * 2]     = lo;
                    part[warp][bg * 4 + bi][cg * 8 + cj * 2 + 1] = hi;
                }
            }
            __syncthreads();

            const float* xgrow = xg + ((size_t)b * SEQ + t) * GATES + hid0;
            #pragma unroll
            for (int g = 0; g < 4; g++) {
                float s = xgrow[g * HID + hl];
                #pragma unroll
                for (int w = 0; w < 8; w++) s += part[w][b][g * 8 + hl];
                gate[g] = s;
            }
            __syncthreads();   // done reading part before next step reuses smem
        }

        // cell update (thread owns (batch b, hidden hid0+hl))
        float ig = sigmoidf_(gate[0]);
        float fg = sigmoidf_(gate[1]);
        float gg = tanhf(gate[2]);
        float og = sigmoidf_(gate[3]);
        c_reg = fg * c_reg + ig * gg;
        float hv = og * tanhf(c_reg);

        g_hbuf[(t + 1) & 1][(hid0 + hl) * 32 + b] = hv;
        out[((size_t)b * SEQ + t) * HID + hid0 + hl] = hv;

        // ---- grid barrier (all 128 blocks co-resident on 148 SMs) ----
        __syncthreads();
        if (tid == 0) {
            __threadfence();
            unsigned int arr = atomicAdd(&g_bar_count, 1);
            if (arr == gridDim.x - 1) {
                atomicExch(&g_bar_count, 0);
                __threadfence();
                atomicAdd(&g_bar_gen, 1);
            } else {
                unsigned int target = start_gen + (unsigned)t + 1u;
                while ((int)(*((volatile unsigned int*)&g_bar_gen) - target) < 0) { }
                __threadfence();
            }
        }
        __syncthreads();
    }
}

// ---------------- launch -------------------------------------------------------
extern "C" void kernel_launch(void* const* d_in, const int* in_sizes, int n_in,
                              void* d_out, int out_size) {
    const float* x    = (const float*)d_in[0];   // [32][512][1024]
    const float* wi   = (const float*)d_in[1];   // [1024][4096]
    const float* wh   = (const float*)d_in[2];   // [1024][4096]
    const float* bias = (const float*)d_in[3];   // [4096]
    float* out = (float*)d_out;                  // [32][512][1024]

    repack_wh<<<NBLK, 256>>>(wh);

    dim3 g1(GATES / 128, MTOT / 128);            // (32, 128)
    gemm_xg<<<g1, 256>>>(x, wi, bias);

    float* xg_ptr;
    float* wp_ptr;
    cudaGetSymbolAddress((void**)&xg_ptr, g_xg);
    cudaGetSymbolAddress((void**)&wp_ptr, g_wpack);
    lstm_rec<<<NBLK, 256>>>(xg_ptr, wp_ptr, out);
}